// round 7
// baseline (speedup 1.0000x reference)
#include <cuda_runtime.h>

// FFM pairwise interactions:
//   inputs: (B=4096, 400, 64) fp32, v[b, j, i, e]
//   output: (B, 1, 190, 64) fp32, out[b,0,p,:] = v[b,jj,ii,:] * v[b,ii,jj,:]
// Pure HBM streaming at the 597 MB algorithmic floor. R6: 256-bit v8 ld/st
// (.cs streaming) + grid-stride ILP=2 -> 4 independent 32-B loads in flight
// per thread with perfect warp coalescing (1024 B contiguous per request).

constexpr int N_FIELDS = 20;
constexpr int NPAIRS   = 190;
constexpr int ROW_FLT  = N_FIELDS * N_FIELDS * 64;   // 25600 floats per batch
constexpr int TOTAL_F8 = 4096 * NPAIRS * 8;          // 6,220,800 32-B chunks
constexpr int ILP      = 2;
constexpr int THREADS  = 256;
constexpr int BLOCKS   = TOTAL_F8 / (THREADS * ILP); // 12150 exact
constexpr int SPAN     = BLOCKS * THREADS;           // grid stride in f8 units

// Per-pair row offsets in floats: offA[p] = (j*20+i)*64, offC[p] = (i*20+j)*64
struct PairTab { int offA[NPAIRS]; int offC[NPAIRS]; };
constexpr PairTab make_tab() {
    PairTab t{};
    int p = 0;
    for (int i = 0; i < N_FIELDS; ++i)
        for (int j = i + 1; j < N_FIELDS; ++j, ++p) {
            t.offA[p] = (j * N_FIELDS + i) * 64;
            t.offC[p] = (i * N_FIELDS + j) * 64;
        }
    return t;
}
__constant__ PairTab TAB = make_tab();

__device__ __forceinline__ void ld256cs(const float* p, float* r) {
    asm volatile("ld.global.cs.v8.f32 {%0,%1,%2,%3,%4,%5,%6,%7}, [%8];"
        : "=f"(r[0]), "=f"(r[1]), "=f"(r[2]), "=f"(r[3]),
          "=f"(r[4]), "=f"(r[5]), "=f"(r[6]), "=f"(r[7])
        : "l"(p));
}

__device__ __forceinline__ void st256cs(float* p, const float* r) {
    asm volatile("st.global.cs.v8.f32 [%0], {%1,%2,%3,%4,%5,%6,%7,%8};"
        :: "l"(p),
           "f"(r[0]), "f"(r[1]), "f"(r[2]), "f"(r[3]),
           "f"(r[4]), "f"(r[5]), "f"(r[6]), "f"(r[7])
        : "memory");
}

__global__ void __launch_bounds__(THREADS)
ffm_pair_kernel(const float* __restrict__ in, float* __restrict__ out)
{
    const int t0 = blockIdx.x * THREADS + threadIdx.x;

    int          f8i[ILP];
    const float* pa[ILP];
    const float* pc[ILP];

    // Address generation for both chunks first (ALU/LDC only).
    #pragma unroll
    for (int k = 0; k < ILP; ++k) {
        int f8 = t0 + k * SPAN;       // exact grid: always < TOTAL_F8
        f8i[k] = f8;
        int q8 = f8 & 7;              // 32-B chunk within the 256-B row
        int bp = f8 >> 3;             // b * NPAIRS + p
        int p  = bp % NPAIRS;         // magic-mul
        int b  = bp / NPAIRS;
        const float* base = in + (long)b * ROW_FLT + q8 * 8;
        pa[k] = base + TAB.offA[p];
        pc[k] = base + TAB.offC[p];
    }

    // 4 independent 256-bit loads in flight.
    float a[ILP][8], c[ILP][8];
    #pragma unroll
    for (int k = 0; k < ILP; ++k) ld256cs(pa[k], a[k]);
    #pragma unroll
    for (int k = 0; k < ILP; ++k) ld256cs(pc[k], c[k]);

    #pragma unroll
    for (int k = 0; k < ILP; ++k) {
        float r[8];
        #pragma unroll
        for (int e = 0; e < 8; ++e) r[e] = a[k][e] * c[k][e];
        st256cs(out + (long)f8i[k] * 8, r);
    }
}

extern "C" void kernel_launch(void* const* d_in, const int* in_sizes, int n_in,
                              void* d_out, int out_size)
{
    const float* in  = (const float*)d_in[0];
    float*       out = (float*)d_out;
    ffm_pair_kernel<<<BLOCKS, THREADS>>>(in, out);
}